// round 2
// baseline (speedup 1.0000x reference)
#include <cuda_runtime.h>
#include <cuda_bf16.h>

// ---------------------------------------------------------------------------
// IterativeEmbeddingModel: 2 iterations of
//   emb <- concat(emb@T1, seg_sum(emb[col],row)@T2, seg_sum_anti(...)@T3)
// R2 changes vs R1:
//  - CSR build forked onto cudaStreamPerThread (overlaps GEMM1; event join
//    before agg1). Graph-capture-legal fork/join off the legacy stream.
//  - scan_tops_kernel (11.6us single-thread!) eliminated: cross-block prefix
//    folded into add_offsets via warp reduction.
//  - scan_partial now shuffle-based (fewer barriers).
//  - GEMM microtile 4x4 -> 2x8: 16 issue slots per 16 FMA-pipe cycles
//    (was 18/16 issue-bound).
// ---------------------------------------------------------------------------

#define NMAX 50000
#define EMAX 400000
#define DIM  192
#define PP   64

typedef unsigned long long ull;

// Scratch (device globals; no allocation APIs allowed)
__device__ int   g_count[2 * NMAX];
__device__ int   g_cursor[2 * NMAX];
__device__ int   g_rowstart[2 * (NMAX + 1)];
__device__ int   g_blocksum[2 * 128];
__device__ int   g_cols[2 * EMAX];
__device__ float g_emb1[(size_t)NMAX * DIM];   // iteration-1 output
__device__ float g_Y[(size_t)NMAX * 128];      // [Y2 | Y3] per row

// ---- packed f32x2 helpers -------------------------------------------------
__device__ __forceinline__ ull pack_dup(float a) {
    ull r; asm("mov.b64 %0, {%1, %1};" : "=l"(r) : "f"(a)); return r;
}
__device__ __forceinline__ void fma2(ull &c, ull a, ull b) {
    asm("fma.rn.f32x2 %0, %1, %2, %0;" : "+l"(c) : "l"(a), "l"(b));
}
__device__ __forceinline__ float2 unpack2(ull v) {
    float2 f; asm("mov.b64 {%0, %1}, %2;" : "=f"(f.x), "=f"(f.y) : "l"(v)); return f;
}

// ---- CSR build ------------------------------------------------------------
__global__ void zero_counts_kernel() {
    int i = blockIdx.x * blockDim.x + threadIdx.x;
    if (i < 2 * NMAX) g_count[i] = 0;
}

__global__ void hist_kernel(const int* __restrict__ e0, const int* __restrict__ e1, int nE) {
    int i = blockIdx.x * blockDim.x + threadIdx.x;
    if (i >= 2 * nE) return;
    int l = (i < nE) ? 0 : 1;
    const int* p = l ? e1 : e0;
    int e = l ? (i - nE) : i;
    int d = p[e];                 // destination row
    atomicAdd(&g_count[l * NMAX + d], 1);
}

// Per-512-block scan (shuffle-based); writes per-element exclusive prefix
// (within block) to g_rowstart and block total to g_blocksum.
__global__ void scan_partial_kernel(int n) {
    __shared__ int warp_sums[16];
    int l = blockIdx.y;
    int i = blockIdx.x * 512 + threadIdx.x;
    int lane = threadIdx.x & 31;
    int w = threadIdx.x >> 5;
    int v = (i < n) ? g_count[l * NMAX + i] : 0;
    // intra-warp inclusive scan
    int s = v;
#pragma unroll
    for (int o = 1; o < 32; o <<= 1) {
        int t = __shfl_up_sync(0xFFFFFFFFu, s, o);
        if (lane >= o) s += t;
    }
    if (lane == 31) warp_sums[w] = s;
    __syncthreads();
    if (w == 0) {
        int ws = (lane < 16) ? warp_sums[lane] : 0;
#pragma unroll
        for (int o = 1; o < 16; o <<= 1) {
            int t = __shfl_up_sync(0xFFFFFFFFu, ws, o);
            if (lane >= o) ws += t;
        }
        if (lane < 16) warp_sums[lane] = ws;
    }
    __syncthreads();
    int base = (w > 0) ? warp_sums[w - 1] : 0;
    if (i < n) g_rowstart[l * (NMAX + 1) + i] = base + s - v;   // exclusive
    if (threadIdx.x == 511) g_blocksum[l * 128 + blockIdx.x] = base + s;
}

// Adds cross-block prefix (computed in-kernel via warp reduce), inits cursor,
// and writes the final total to g_rowstart[l][n]. Replaces scan_tops.
__global__ void add_offsets_kernel(int n, int nb) {
    int l = blockIdx.y;
    int i = blockIdx.x * blockDim.x + threadIdx.x;
    __shared__ int sP;
    // All indices in this 256-thread block share the same 512-chunk (>>9)
    // because blockIdx.x*256 spans exactly half a chunk.
    if (threadIdx.x < 32) {
        int myblk = blockIdx.x >> 1;           // 512-chunk index
        int s = 0;
        for (int b = threadIdx.x; b < myblk; b += 32) s += g_blocksum[l * 128 + b];
#pragma unroll
        for (int o = 16; o; o >>= 1) s += __shfl_xor_sync(0xFFFFFFFFu, s, o);
        if (threadIdx.x == 0) sP = s;
    }
    if (blockIdx.x == 0 && threadIdx.x >= 32 && threadIdx.x < 64) {
        int lane = threadIdx.x - 32;
        int s = 0;
        for (int b = lane; b < nb; b += 32) s += g_blocksum[l * 128 + b];
#pragma unroll
        for (int o = 16; o; o >>= 1) s += __shfl_xor_sync(0xFFFFFFFFu, s, o);
        if (lane == 0) g_rowstart[l * (NMAX + 1) + n] = s;   // grand total
    }
    __syncthreads();
    if (i < n) {
        g_rowstart[l * (NMAX + 1) + i] += sP;
        g_cursor[l * NMAX + i] = 0;
    }
}

__global__ void fill_kernel(const int* __restrict__ e0, const int* __restrict__ e1, int nE) {
    int i = blockIdx.x * blockDim.x + threadIdx.x;
    if (i >= 2 * nE) return;
    int l = (i < nE) ? 0 : 1;
    const int* p = l ? e1 : e0;
    int e = l ? (i - nE) : i;
    int d = p[e];
    int c = p[nE + e];
    int pos = g_rowstart[l * (NMAX + 1) + d] + atomicAdd(&g_cursor[l * NMAX + d], 1);
    g_cols[l * EMAX + pos] = c;
}

// ---- GEMM: Y = A @ [T0|T1|T2]; T0 part straight to dst cols[0:64] ---------
// BM=64 rows/block, 256 threads, per-theta 2x8 micro-tile (ty: 32 row-groups
// of 2, tx: 8 col-groups of 8). Per k: 2 LDS(A)+2 mov64+4 LDS64(B)+8 FMA2
// = 16 issue slots against 16 FMA-pipe cycles -> FMA-bound.
#define GEMM_SMEM_BYTES ((64 * 193 + DIM * PP) * 4)

__global__ __launch_bounds__(256, 2)
void gemm_kernel(const float* __restrict__ A,
                 const float* __restrict__ T0,
                 const float* __restrict__ T1,
                 const float* __restrict__ T2,
                 float* __restrict__ dst,   // n x 192 (cols 0:64 written here)
                 float* __restrict__ Y,     // n x 128 (Y2|Y3)
                 int n)
{
    extern __shared__ float sm[];
    float* As = sm;                  // [64][193]
    float* Bs = sm + 64 * 193;       // [192][64]
    const int tid = threadIdx.x;
    const int tx = tid & 7;          // col group (8 cols)
    const int ty = tid >> 3;         // row group (2 rows)
    const int rowBase = blockIdx.x * 64;

    // Load A tile (64 x 192), zero-pad OOB rows
    for (int f = tid; f < 64 * 48; f += 256) {
        int r = f / 48, c4 = f % 48;
        int gr = rowBase + r;
        float4 v = make_float4(0.f, 0.f, 0.f, 0.f);
        if (gr < n) v = *(const float4*)(A + (size_t)gr * DIM + c4 * 4);
        float* d = As + r * 193 + c4 * 4;
        d[0] = v.x; d[1] = v.y; d[2] = v.z; d[3] = v.w;
    }

    const float* Tarr[3] = {T0, T1, T2};
#pragma unroll
    for (int t = 0; t < 3; ++t) {
        __syncthreads();
        const float4* Tp = (const float4*)Tarr[t];
        float4* B4 = (float4*)Bs;
        for (int f = tid; f < DIM * PP / 4; f += 256) B4[f] = Tp[f];
        __syncthreads();

        ull acc0[4] = {0, 0, 0, 0};
        ull acc1[4] = {0, 0, 0, 0};
        const float* Ap0 = As + (ty * 2) * 193;
        const float* Ap1 = Ap0 + 193;
        const float* Bp = Bs + tx * 8;
#pragma unroll 4
        for (int k = 0; k < DIM; k++) {
            ull b0 = *(const ull*)(Bp + k * 64 + 0);
            ull b1 = *(const ull*)(Bp + k * 64 + 2);
            ull b2 = *(const ull*)(Bp + k * 64 + 4);
            ull b3 = *(const ull*)(Bp + k * 64 + 6);
            ull a0 = pack_dup(Ap0[k]);
            ull a1 = pack_dup(Ap1[k]);
            fma2(acc0[0], a0, b0); fma2(acc0[1], a0, b1);
            fma2(acc0[2], a0, b2); fma2(acc0[3], a0, b3);
            fma2(acc1[0], a1, b0); fma2(acc1[1], a1, b1);
            fma2(acc1[2], a1, b2); fma2(acc1[3], a1, b3);
        }

#pragma unroll
        for (int i = 0; i < 2; i++) {
            ull* acc = i ? acc1 : acc0;
            int gr = rowBase + ty * 2 + i;
            if (gr < n) {
                float2 p0 = unpack2(acc[0]);
                float2 p1 = unpack2(acc[1]);
                float2 p2 = unpack2(acc[2]);
                float2 p3 = unpack2(acc[3]);
                float4 vlo = make_float4(p0.x, p0.y, p1.x, p1.y);
                float4 vhi = make_float4(p2.x, p2.y, p3.x, p3.y);
                if (t == 0) {
                    *(float4*)(dst + (size_t)gr * DIM + tx * 8)     = vlo;
                    *(float4*)(dst + (size_t)gr * DIM + tx * 8 + 4) = vhi;
                } else {
                    *(float4*)(Y + (size_t)gr * 128 + (t - 1) * 64 + tx * 8)     = vlo;
                    *(float4*)(Y + (size_t)gr * 128 + (t - 1) * 64 + tx * 8 + 4) = vhi;
                }
            }
        }
    }
}

// ---- Aggregation: warp per node, atomic-free CSR gather -------------------
__global__ void agg_kernel(const float* __restrict__ Y, float* __restrict__ dst, int n)
{
    int gw = (blockIdx.x * blockDim.x + threadIdx.x) >> 5;
    int lane = threadIdx.x & 31;
    if (gw >= n) return;
#pragma unroll
    for (int l = 0; l < 2; ++l) {
        const int* rs = g_rowstart + l * (NMAX + 1);
        const int* cs = g_cols + l * EMAX;
        int s = __ldg(rs + gw);
        int e = __ldg(rs + gw + 1);
        const float* Yb = Y + l * 64 + lane * 2;
        float ax = 0.f, ay = 0.f;
        int j = s;
        for (; j + 4 <= e; j += 4) {        // unroll-4 for MLP
            int c0 = cs[j], c1 = cs[j + 1], c2 = cs[j + 2], c3 = cs[j + 3];
            float2 v0 = *(const float2*)(Yb + (size_t)c0 * 128);
            float2 v1 = *(const float2*)(Yb + (size_t)c1 * 128);
            float2 v2 = *(const float2*)(Yb + (size_t)c2 * 128);
            float2 v3 = *(const float2*)(Yb + (size_t)c3 * 128);
            ax += (v0.x + v1.x) + (v2.x + v3.x);
            ay += (v0.y + v1.y) + (v2.y + v3.y);
        }
        for (; j < e; ++j) {
            float2 v = *(const float2*)(Yb + (size_t)cs[j] * 128);
            ax += v.x; ay += v.y;
        }
        float2 o = make_float2(ax, ay);
        *(float2*)(dst + (size_t)gw * DIM + 64 + l * 64 + lane * 2) = o;
    }
}

// ---------------------------------------------------------------------------
extern "C" void kernel_launch(void* const* d_in, const int* in_sizes, int n_in,
                              void* d_out, int out_size)
{
    const float* emb = (const float*)d_in[0];
    const float* t1  = (const float*)d_in[1];
    const float* t2  = (const float*)d_in[2];
    const float* t3  = (const float*)d_in[3];
    const int*   e0  = (const int*)d_in[4];
    const int*   e1  = (const int*)d_in[5];

    int n  = in_sizes[0] / DIM;
    int nE = in_sizes[4] / 2;
    float* out = (float*)d_out;

    void *p_emb1_v, *p_Y_v;
    cudaGetSymbolAddress(&p_emb1_v, g_emb1);
    cudaGetSymbolAddress(&p_Y_v, g_Y);
    float* p_emb1 = (float*)p_emb1_v;
    float* p_Y    = (float*)p_Y_v;

    cudaFuncSetAttribute(gemm_kernel, cudaFuncAttributeMaxDynamicSharedMemorySize,
                         GEMM_SMEM_BYTES);

    // Fork/join events (DisableTiming: no device memory). Created per call,
    // intentionally not destroyed (capture-safe; 2 calls total).
    cudaEvent_t evFork, evJoin;
    cudaEventCreateWithFlags(&evFork, cudaEventDisableTiming);
    cudaEventCreateWithFlags(&evJoin, cudaEventDisableTiming);

    cudaStream_t side = cudaStreamPerThread;

    // Fork side stream from the (possibly capturing) legacy stream.
    cudaEventRecord(evFork, 0);
    cudaStreamWaitEvent(side, evFork, 0);

    // --- CSR build on side stream (overlaps GEMM1) ---
    int nb = (n + 511) / 512;
    zero_counts_kernel<<<(2 * NMAX + 255) / 256, 256, 0, side>>>();
    hist_kernel<<<(2 * nE + 255) / 256, 256, 0, side>>>(e0, e1, nE);
    dim3 gscan(nb, 2);
    scan_partial_kernel<<<gscan, 512, 0, side>>>(n);
    dim3 goff((n + 255) / 256, 2);
    add_offsets_kernel<<<goff, 256, 0, side>>>(n, nb);
    fill_kernel<<<(2 * nE + 255) / 256, 256, 0, side>>>(e0, e1, nE);
    cudaEventRecord(evJoin, side);

    int gemm_blocks = (n + 63) / 64;
    int agg_blocks = (n * 32 + 255) / 256;

    // --- iteration 1 (GEMM1 on legacy, concurrent with CSR build) ---
    gemm_kernel<<<gemm_blocks, 256, GEMM_SMEM_BYTES>>>(emb, t1, t2, t3, p_emb1, p_Y, n);
    cudaStreamWaitEvent(0, evJoin, 0);   // join: agg needs the CSR
    agg_kernel<<<agg_blocks, 256>>>(p_Y, p_emb1, n);

    // --- iteration 2 ---
    gemm_kernel<<<gemm_blocks, 256, GEMM_SMEM_BYTES>>>(p_emb1, t1, t2, t3, out, p_Y, n);
    agg_kernel<<<agg_blocks, 256>>>(p_Y, out, n);
}

// round 3
// speedup vs baseline: 1.0001x; 1.0001x over previous
#include <cuda_runtime.h>
#include <cuda_bf16.h>

// ---------------------------------------------------------------------------
// IterativeEmbeddingModel: 2 iterations of
//   emb <- concat(emb@T1, seg_sum(emb[col],row)@T2, seg_sum_anti(...)@T3)
// R3: revert R2's stream fork (2x regression from cross-stream capture).
//     Single stream. Keep: shuffle scan + fused cross-block prefix (no
//     single-thread scan_tops), 2x8 GEMM microtile (issue-balanced).
// ---------------------------------------------------------------------------

#define NMAX 50000
#define EMAX 400000
#define DIM  192
#define PP   64

typedef unsigned long long ull;

// Scratch (device globals; no allocation APIs allowed)
__device__ int   g_count[2 * NMAX];
__device__ int   g_cursor[2 * NMAX];
__device__ int   g_rowstart[2 * (NMAX + 1)];
__device__ int   g_blocksum[2 * 128];
__device__ int   g_cols[2 * EMAX];
__device__ float g_emb1[(size_t)NMAX * DIM];   // iteration-1 output
__device__ float g_Y[(size_t)NMAX * 128];      // [Y2 | Y3] per row

// ---- packed f32x2 helpers -------------------------------------------------
__device__ __forceinline__ ull pack_dup(float a) {
    ull r; asm("mov.b64 %0, {%1, %1};" : "=l"(r) : "f"(a)); return r;
}
__device__ __forceinline__ void fma2(ull &c, ull a, ull b) {
    asm("fma.rn.f32x2 %0, %1, %2, %0;" : "+l"(c) : "l"(a), "l"(b));
}
__device__ __forceinline__ float2 unpack2(ull v) {
    float2 f; asm("mov.b64 {%0, %1}, %2;" : "=f"(f.x), "=f"(f.y) : "l"(v)); return f;
}

// ---- CSR build ------------------------------------------------------------
__global__ void zero_counts_kernel() {
    int i = blockIdx.x * blockDim.x + threadIdx.x;
    if (i < 2 * NMAX) g_count[i] = 0;
}

__global__ void hist_kernel(const int* __restrict__ e0, const int* __restrict__ e1, int nE) {
    int i = blockIdx.x * blockDim.x + threadIdx.x;
    if (i >= 2 * nE) return;
    int l = (i < nE) ? 0 : 1;
    const int* p = l ? e1 : e0;
    int e = l ? (i - nE) : i;
    int d = p[e];                 // destination row
    atomicAdd(&g_count[l * NMAX + d], 1);
}

// Per-512-block scan (shuffle-based); writes per-element exclusive prefix
// (within block) to g_rowstart and block total to g_blocksum.
__global__ void scan_partial_kernel(int n) {
    __shared__ int warp_sums[16];
    int l = blockIdx.y;
    int i = blockIdx.x * 512 + threadIdx.x;
    int lane = threadIdx.x & 31;
    int w = threadIdx.x >> 5;
    int v = (i < n) ? g_count[l * NMAX + i] : 0;
    int s = v;
#pragma unroll
    for (int o = 1; o < 32; o <<= 1) {
        int t = __shfl_up_sync(0xFFFFFFFFu, s, o);
        if (lane >= o) s += t;
    }
    if (lane == 31) warp_sums[w] = s;
    __syncthreads();
    if (w == 0) {
        int ws = (lane < 16) ? warp_sums[lane] : 0;
#pragma unroll
        for (int o = 1; o < 16; o <<= 1) {
            int t = __shfl_up_sync(0xFFFFFFFFu, ws, o);
            if (lane >= o) ws += t;
        }
        if (lane < 16) warp_sums[lane] = ws;
    }
    __syncthreads();
    int base = (w > 0) ? warp_sums[w - 1] : 0;
    if (i < n) g_rowstart[l * (NMAX + 1) + i] = base + s - v;   // exclusive
    if (threadIdx.x == 511) g_blocksum[l * 128 + blockIdx.x] = base + s;
}

// Adds cross-block prefix (warp reduce over block sums), inits cursor,
// writes grand total to g_rowstart[l][n]. Replaces the single-thread scan_tops.
__global__ void add_offsets_kernel(int n, int nb) {
    int l = blockIdx.y;
    int i = blockIdx.x * blockDim.x + threadIdx.x;
    __shared__ int sP;
    if (threadIdx.x < 32) {
        int myblk = blockIdx.x >> 1;           // 512-chunk index (256-thread blocks)
        int s = 0;
        for (int b = threadIdx.x; b < myblk; b += 32) s += g_blocksum[l * 128 + b];
#pragma unroll
        for (int o = 16; o; o >>= 1) s += __shfl_xor_sync(0xFFFFFFFFu, s, o);
        if (threadIdx.x == 0) sP = s;
    }
    if (blockIdx.x == 0 && threadIdx.x >= 32 && threadIdx.x < 64) {
        int lane = threadIdx.x - 32;
        int s = 0;
        for (int b = lane; b < nb; b += 32) s += g_blocksum[l * 128 + b];
#pragma unroll
        for (int o = 16; o; o >>= 1) s += __shfl_xor_sync(0xFFFFFFFFu, s, o);
        if (lane == 0) g_rowstart[l * (NMAX + 1) + n] = s;   // grand total
    }
    __syncthreads();
    if (i < n) {
        g_rowstart[l * (NMAX + 1) + i] += sP;
        g_cursor[l * NMAX + i] = 0;
    }
}

__global__ void fill_kernel(const int* __restrict__ e0, const int* __restrict__ e1, int nE) {
    int i = blockIdx.x * blockDim.x + threadIdx.x;
    if (i >= 2 * nE) return;
    int l = (i < nE) ? 0 : 1;
    const int* p = l ? e1 : e0;
    int e = l ? (i - nE) : i;
    int d = p[e];
    int c = p[nE + e];
    int pos = g_rowstart[l * (NMAX + 1) + d] + atomicAdd(&g_cursor[l * NMAX + d], 1);
    g_cols[l * EMAX + pos] = c;
}

// ---- GEMM: Y = A @ [T0|T1|T2]; T0 part straight to dst cols[0:64] ---------
// BM=64 rows/block, 256 threads, per-theta 2x8 micro-tile.
// Per k: 2 LDS(A) + 2 pack + 4 LDS64(B) + 8 FMA2 = 16 issue slots against
// 16 FMA-pipe cycles -> FMA-bound.
#define GEMM_SMEM_BYTES ((64 * 193 + DIM * PP) * 4)

__global__ __launch_bounds__(256, 2)
void gemm_kernel(const float* __restrict__ A,
                 const float* __restrict__ T0,
                 const float* __restrict__ T1,
                 const float* __restrict__ T2,
                 float* __restrict__ dst,   // n x 192 (cols 0:64 written here)
                 float* __restrict__ Y,     // n x 128 (Y2|Y3)
                 int n)
{
    extern __shared__ float sm[];
    float* As = sm;                  // [64][193]
    float* Bs = sm + 64 * 193;       // [192][64]
    const int tid = threadIdx.x;
    const int tx = tid & 7;          // col group (8 cols)
    const int ty = tid >> 3;         // row group (2 rows)
    const int rowBase = blockIdx.x * 64;

    // Load A tile (64 x 192), zero-pad OOB rows
    for (int f = tid; f < 64 * 48; f += 256) {
        int r = f / 48, c4 = f % 48;
        int gr = rowBase + r;
        float4 v = make_float4(0.f, 0.f, 0.f, 0.f);
        if (gr < n) v = *(const float4*)(A + (size_t)gr * DIM + c4 * 4);
        float* d = As + r * 193 + c4 * 4;
        d[0] = v.x; d[1] = v.y; d[2] = v.z; d[3] = v.w;
    }

    const float* Tarr[3] = {T0, T1, T2};
#pragma unroll
    for (int t = 0; t < 3; ++t) {
        __syncthreads();
        const float4* Tp = (const float4*)Tarr[t];
        float4* B4 = (float4*)Bs;
        for (int f = tid; f < DIM * PP / 4; f += 256) B4[f] = Tp[f];
        __syncthreads();

        ull acc0[4] = {0, 0, 0, 0};
        ull acc1[4] = {0, 0, 0, 0};
        const float* Ap0 = As + (ty * 2) * 193;
        const float* Ap1 = Ap0 + 193;
        const float* Bp = Bs + tx * 8;
#pragma unroll 4
        for (int k = 0; k < DIM; k++) {
            ull b0 = *(const ull*)(Bp + k * 64 + 0);
            ull b1 = *(const ull*)(Bp + k * 64 + 2);
            ull b2 = *(const ull*)(Bp + k * 64 + 4);
            ull b3 = *(const ull*)(Bp + k * 64 + 6);
            ull a0 = pack_dup(Ap0[k]);
            ull a1 = pack_dup(Ap1[k]);
            fma2(acc0[0], a0, b0); fma2(acc0[1], a0, b1);
            fma2(acc0[2], a0, b2); fma2(acc0[3], a0, b3);
            fma2(acc1[0], a1, b0); fma2(acc1[1], a1, b1);
            fma2(acc1[2], a1, b2); fma2(acc1[3], a1, b3);
        }

#pragma unroll
        for (int i = 0; i < 2; i++) {
            ull* acc = i ? acc1 : acc0;
            int gr = rowBase + ty * 2 + i;
            if (gr < n) {
                float2 p0 = unpack2(acc[0]);
                float2 p1 = unpack2(acc[1]);
                float2 p2 = unpack2(acc[2]);
                float2 p3 = unpack2(acc[3]);
                float4 vlo = make_float4(p0.x, p0.y, p1.x, p1.y);
                float4 vhi = make_float4(p2.x, p2.y, p3.x, p3.y);
                if (t == 0) {
                    *(float4*)(dst + (size_t)gr * DIM + tx * 8)     = vlo;
                    *(float4*)(dst + (size_t)gr * DIM + tx * 8 + 4) = vhi;
                } else {
                    *(float4*)(Y + (size_t)gr * 128 + (t - 1) * 64 + tx * 8)     = vlo;
                    *(float4*)(Y + (size_t)gr * 128 + (t - 1) * 64 + tx * 8 + 4) = vhi;
                }
            }
        }
    }
}

// ---- Aggregation: warp per node, atomic-free CSR gather -------------------
__global__ void agg_kernel(const float* __restrict__ Y, float* __restrict__ dst, int n)
{
    int gw = (blockIdx.x * blockDim.x + threadIdx.x) >> 5;
    int lane = threadIdx.x & 31;
    if (gw >= n) return;
#pragma unroll
    for (int l = 0; l < 2; ++l) {
        const int* rs = g_rowstart + l * (NMAX + 1);
        const int* cs = g_cols + l * EMAX;
        int s = __ldg(rs + gw);
        int e = __ldg(rs + gw + 1);
        const float* Yb = Y + l * 64 + lane * 2;
        float ax = 0.f, ay = 0.f;
        int j = s;
        for (; j + 4 <= e; j += 4) {        // unroll-4 for MLP
            int c0 = cs[j], c1 = cs[j + 1], c2 = cs[j + 2], c3 = cs[j + 3];
            float2 v0 = *(const float2*)(Yb + (size_t)c0 * 128);
            float2 v1 = *(const float2*)(Yb + (size_t)c1 * 128);
            float2 v2 = *(const float2*)(Yb + (size_t)c2 * 128);
            float2 v3 = *(const float2*)(Yb + (size_t)c3 * 128);
            ax += (v0.x + v1.x) + (v2.x + v3.x);
            ay += (v0.y + v1.y) + (v2.y + v3.y);
        }
        for (; j < e; ++j) {
            float2 v = *(const float2*)(Yb + (size_t)cs[j] * 128);
            ax += v.x; ay += v.y;
        }
        float2 o = make_float2(ax, ay);
        *(float2*)(dst + (size_t)gw * DIM + 64 + l * 64 + lane * 2) = o;
    }
}

// ---------------------------------------------------------------------------
extern "C" void kernel_launch(void* const* d_in, const int* in_sizes, int n_in,
                              void* d_out, int out_size)
{
    const float* emb = (const float*)d_in[0];
    const float* t1  = (const float*)d_in[1];
    const float* t2  = (const float*)d_in[2];
    const float* t3  = (const float*)d_in[3];
    const int*   e0  = (const int*)d_in[4];
    const int*   e1  = (const int*)d_in[5];

    int n  = in_sizes[0] / DIM;
    int nE = in_sizes[4] / 2;
    float* out = (float*)d_out;

    void *p_emb1_v, *p_Y_v;
    cudaGetSymbolAddress(&p_emb1_v, g_emb1);
    cudaGetSymbolAddress(&p_Y_v, g_Y);
    float* p_emb1 = (float*)p_emb1_v;
    float* p_Y    = (float*)p_Y_v;

    cudaFuncSetAttribute(gemm_kernel, cudaFuncAttributeMaxDynamicSharedMemorySize,
                         GEMM_SMEM_BYTES);

    // --- CSR build (single stream; once, shared by both iterations) ---
    int nb = (n + 511) / 512;
    zero_counts_kernel<<<(2 * NMAX + 255) / 256, 256>>>();
    hist_kernel<<<(2 * nE + 255) / 256, 256>>>(e0, e1, nE);
    dim3 gscan(nb, 2);
    scan_partial_kernel<<<gscan, 512>>>(n);
    dim3 goff((n + 255) / 256, 2);
    add_offsets_kernel<<<goff, 256>>>(n, nb);
    fill_kernel<<<(2 * nE + 255) / 256, 256>>>(e0, e1, nE);

    int gemm_blocks = (n + 63) / 64;
    int agg_blocks = (n * 32 + 255) / 256;

    // --- iteration 1 ---
    gemm_kernel<<<gemm_blocks, 256, GEMM_SMEM_BYTES>>>(emb, t1, t2, t3, p_emb1, p_Y, n);
    agg_kernel<<<agg_blocks, 256>>>(p_Y, p_emb1, n);

    // --- iteration 2 ---
    gemm_kernel<<<gemm_blocks, 256, GEMM_SMEM_BYTES>>>(p_emb1, t1, t2, t3, out, p_Y, n);
    agg_kernel<<<agg_blocks, 256>>>(p_Y, out, n);
}

// round 4
// speedup vs baseline: 1.9291x; 1.9290x over previous
#include <cuda_runtime.h>
#include <cuda_bf16.h>

// ---------------------------------------------------------------------------
// IterativeEmbeddingModel: 2 iterations of
//   emb <- concat(emb@T1, seg_sum(emb[col],row)@T2, seg_sum_anti(...)@T3)
// R4: GEMM reverted to the exact R1 body (named scalar accumulators, 4x4
//     microtile). R2/R3's 2x8 version selected local accumulator arrays
//     through a runtime pointer -> suspected local-memory spill -> 2x total
//     regression. Scan improvements from R2 kept (no single-thread scan_tops).
// ---------------------------------------------------------------------------

#define NMAX 50000
#define EMAX 400000
#define DIM  192
#define PP   64

typedef unsigned long long ull;

// Scratch (device globals; no allocation APIs allowed)
__device__ int   g_count[2 * NMAX];
__device__ int   g_cursor[2 * NMAX];
__device__ int   g_rowstart[2 * (NMAX + 1)];
__device__ int   g_blocksum[2 * 128];
__device__ int   g_cols[2 * EMAX];
__device__ float g_emb1[(size_t)NMAX * DIM];   // iteration-1 output
__device__ float g_Y[(size_t)NMAX * 128];      // [Y2 | Y3] per row

// ---- packed f32x2 helpers -------------------------------------------------
__device__ __forceinline__ ull pack_dup(float a) {
    ull r; asm("mov.b64 %0, {%1, %1};" : "=l"(r) : "f"(a)); return r;
}
__device__ __forceinline__ void fma2(ull &c, ull a, ull b) {
    asm("fma.rn.f32x2 %0, %1, %2, %0;" : "+l"(c) : "l"(a), "l"(b));
}
__device__ __forceinline__ float2 unpack2(ull v) {
    float2 f; asm("mov.b64 {%0, %1}, %2;" : "=f"(f.x), "=f"(f.y) : "l"(v)); return f;
}

// ---- CSR build ------------------------------------------------------------
__global__ void zero_counts_kernel() {
    int i = blockIdx.x * blockDim.x + threadIdx.x;
    if (i < 2 * NMAX) g_count[i] = 0;
}

__global__ void hist_kernel(const int* __restrict__ e0, const int* __restrict__ e1, int nE) {
    int i = blockIdx.x * blockDim.x + threadIdx.x;
    if (i >= 2 * nE) return;
    int l = (i < nE) ? 0 : 1;
    const int* p = l ? e1 : e0;
    int e = l ? (i - nE) : i;
    int d = p[e];                 // destination row
    atomicAdd(&g_count[l * NMAX + d], 1);
}

// Per-512-block scan (shuffle-based); writes per-element exclusive prefix
// (within block) to g_rowstart and block total to g_blocksum.
__global__ void scan_partial_kernel(int n) {
    __shared__ int warp_sums[16];
    int l = blockIdx.y;
    int i = blockIdx.x * 512 + threadIdx.x;
    int lane = threadIdx.x & 31;
    int w = threadIdx.x >> 5;
    int v = (i < n) ? g_count[l * NMAX + i] : 0;
    int s = v;
#pragma unroll
    for (int o = 1; o < 32; o <<= 1) {
        int t = __shfl_up_sync(0xFFFFFFFFu, s, o);
        if (lane >= o) s += t;
    }
    if (lane == 31) warp_sums[w] = s;
    __syncthreads();
    if (w == 0) {
        int ws = (lane < 16) ? warp_sums[lane] : 0;
#pragma unroll
        for (int o = 1; o < 16; o <<= 1) {
            int t = __shfl_up_sync(0xFFFFFFFFu, ws, o);
            if (lane >= o) ws += t;
        }
        if (lane < 16) warp_sums[lane] = ws;
    }
    __syncthreads();
    int base = (w > 0) ? warp_sums[w - 1] : 0;
    if (i < n) g_rowstart[l * (NMAX + 1) + i] = base + s - v;   // exclusive
    if (threadIdx.x == 511) g_blocksum[l * 128 + blockIdx.x] = base + s;
}

// Adds cross-block prefix (warp reduce over block sums), inits cursor,
// writes grand total to g_rowstart[l][n]. Replaces the single-thread scan_tops.
__global__ void add_offsets_kernel(int n, int nb) {
    int l = blockIdx.y;
    int i = blockIdx.x * blockDim.x + threadIdx.x;
    __shared__ int sP;
    if (threadIdx.x < 32) {
        int myblk = blockIdx.x >> 1;           // 512-chunk index (256-thread blocks)
        int s = 0;
        for (int b = threadIdx.x; b < myblk; b += 32) s += g_blocksum[l * 128 + b];
#pragma unroll
        for (int o = 16; o; o >>= 1) s += __shfl_xor_sync(0xFFFFFFFFu, s, o);
        if (threadIdx.x == 0) sP = s;
    }
    if (blockIdx.x == 0 && threadIdx.x >= 32 && threadIdx.x < 64) {
        int lane = threadIdx.x - 32;
        int s = 0;
        for (int b = lane; b < nb; b += 32) s += g_blocksum[l * 128 + b];
#pragma unroll
        for (int o = 16; o; o >>= 1) s += __shfl_xor_sync(0xFFFFFFFFu, s, o);
        if (lane == 0) g_rowstart[l * (NMAX + 1) + n] = s;   // grand total
    }
    __syncthreads();
    if (i < n) {
        g_rowstart[l * (NMAX + 1) + i] += sP;
        g_cursor[l * NMAX + i] = 0;
    }
}

__global__ void fill_kernel(const int* __restrict__ e0, const int* __restrict__ e1, int nE) {
    int i = blockIdx.x * blockDim.x + threadIdx.x;
    if (i >= 2 * nE) return;
    int l = (i < nE) ? 0 : 1;
    const int* p = l ? e1 : e0;
    int e = l ? (i - nE) : i;
    int d = p[e];
    int c = p[nE + e];
    int pos = g_rowstart[l * (NMAX + 1) + d] + atomicAdd(&g_cursor[l * NMAX + d], 1);
    g_cols[l * EMAX + pos] = c;
}

// ---- GEMM: Y = A @ [T0|T1|T2]; T0 part straight to dst cols[0:64] ---------
// EXACT R1 body: BM=64 rows/block, 256 threads = 16x16, 4x4 micro-tile,
// named scalar ull accumulators (register-resident, no spill risk).
#define GEMM_SMEM_BYTES ((64 * 193 + DIM * PP) * 4)

__global__ __launch_bounds__(256, 2)
void gemm_kernel(const float* __restrict__ A,
                 const float* __restrict__ T0,
                 const float* __restrict__ T1,
                 const float* __restrict__ T2,
                 float* __restrict__ dst,   // n x 192 (cols 0:64 written here)
                 float* __restrict__ Y,     // n x 128 (Y2|Y3)
                 int n)
{
    extern __shared__ float sm[];
    float* As = sm;                  // [64][193]
    float* Bs = sm + 64 * 193;       // [192][64]
    const int tid = threadIdx.x;
    const int tx = tid & 15, ty = tid >> 4;
    const int rowBase = blockIdx.x * 64;

    // Load A tile (64 x 192), zero-pad OOB rows
    for (int f = tid; f < 64 * 48; f += 256) {
        int r = f / 48, c4 = f % 48;
        int gr = rowBase + r;
        float4 v = make_float4(0.f, 0.f, 0.f, 0.f);
        if (gr < n) v = *(const float4*)(A + (size_t)gr * DIM + c4 * 4);
        float* d = As + r * 193 + c4 * 4;
        d[0] = v.x; d[1] = v.y; d[2] = v.z; d[3] = v.w;
    }

    const float* Tarr[3] = {T0, T1, T2};
#pragma unroll
    for (int t = 0; t < 3; ++t) {
        __syncthreads();
        const float4* Tp = (const float4*)Tarr[t];
        float4* B4 = (float4*)Bs;
        for (int f = tid; f < DIM * PP / 4; f += 256) B4[f] = Tp[f];
        __syncthreads();

        ull acc00 = 0, acc01 = 0, acc10 = 0, acc11 = 0;
        ull acc20 = 0, acc21 = 0, acc30 = 0, acc31 = 0;
        const float* Ap = As + (ty * 4) * 193;
#pragma unroll 4
        for (int k = 0; k < DIM; k++) {
            ull b01 = *(const ull*)(Bs + k * 64 + tx * 4);
            ull b23 = *(const ull*)(Bs + k * 64 + tx * 4 + 2);
            ull a0 = pack_dup(Ap[0 * 193 + k]);
            ull a1 = pack_dup(Ap[1 * 193 + k]);
            ull a2 = pack_dup(Ap[2 * 193 + k]);
            ull a3 = pack_dup(Ap[3 * 193 + k]);
            fma2(acc00, a0, b01); fma2(acc01, a0, b23);
            fma2(acc10, a1, b01); fma2(acc11, a1, b23);
            fma2(acc20, a2, b01); fma2(acc21, a2, b23);
            fma2(acc30, a3, b01); fma2(acc31, a3, b23);
        }

        ull accs[4][2] = {{acc00, acc01}, {acc10, acc11}, {acc20, acc21}, {acc30, acc31}};
#pragma unroll
        for (int i = 0; i < 4; i++) {
            int gr = rowBase + ty * 4 + i;
            if (gr < n) {
                float2 lo = unpack2(accs[i][0]);
                float2 hi = unpack2(accs[i][1]);
                float4 v = make_float4(lo.x, lo.y, hi.x, hi.y);
                if (t == 0) *(float4*)(dst + (size_t)gr * DIM + tx * 4) = v;
                else        *(float4*)(Y + (size_t)gr * 128 + (t - 1) * 64 + tx * 4) = v;
            }
        }
    }
}

// ---- Aggregation: warp per node, atomic-free CSR gather -------------------
__global__ void agg_kernel(const float* __restrict__ Y, float* __restrict__ dst, int n)
{
    int gw = (blockIdx.x * blockDim.x + threadIdx.x) >> 5;
    int lane = threadIdx.x & 31;
    if (gw >= n) return;
#pragma unroll
    for (int l = 0; l < 2; ++l) {
        const int* rs = g_rowstart + l * (NMAX + 1);
        const int* cs = g_cols + l * EMAX;
        int s = __ldg(rs + gw);
        int e = __ldg(rs + gw + 1);
        const float* Yb = Y + l * 64 + lane * 2;
        float ax = 0.f, ay = 0.f;
        int j = s;
        for (; j + 4 <= e; j += 4) {        // unroll-4 for MLP
            int c0 = cs[j], c1 = cs[j + 1], c2 = cs[j + 2], c3 = cs[j + 3];
            float2 v0 = *(const float2*)(Yb + (size_t)c0 * 128);
            float2 v1 = *(const float2*)(Yb + (size_t)c1 * 128);
            float2 v2 = *(const float2*)(Yb + (size_t)c2 * 128);
            float2 v3 = *(const float2*)(Yb + (size_t)c3 * 128);
            ax += (v0.x + v1.x) + (v2.x + v3.x);
            ay += (v0.y + v1.y) + (v2.y + v3.y);
        }
        for (; j < e; ++j) {
            float2 v = *(const float2*)(Yb + (size_t)cs[j] * 128);
            ax += v.x; ay += v.y;
        }
        float2 o = make_float2(ax, ay);
        *(float2*)(dst + (size_t)gw * DIM + 64 + l * 64 + lane * 2) = o;
    }
}

// ---------------------------------------------------------------------------
extern "C" void kernel_launch(void* const* d_in, const int* in_sizes, int n_in,
                              void* d_out, int out_size)
{
    const float* emb = (const float*)d_in[0];
    const float* t1  = (const float*)d_in[1];
    const float* t2  = (const float*)d_in[2];
    const float* t3  = (const float*)d_in[3];
    const int*   e0  = (const int*)d_in[4];
    const int*   e1  = (const int*)d_in[5];

    int n  = in_sizes[0] / DIM;
    int nE = in_sizes[4] / 2;
    float* out = (float*)d_out;

    void *p_emb1_v, *p_Y_v;
    cudaGetSymbolAddress(&p_emb1_v, g_emb1);
    cudaGetSymbolAddress(&p_Y_v, g_Y);
    float* p_emb1 = (float*)p_emb1_v;
    float* p_Y    = (float*)p_Y_v;

    cudaFuncSetAttribute(gemm_kernel, cudaFuncAttributeMaxDynamicSharedMemorySize,
                         GEMM_SMEM_BYTES);

    // --- CSR build (single stream; once, shared by both iterations) ---
    int nb = (n + 511) / 512;
    zero_counts_kernel<<<(2 * NMAX + 255) / 256, 256>>>();
    hist_kernel<<<(2 * nE + 255) / 256, 256>>>(e0, e1, nE);
    dim3 gscan(nb, 2);
    scan_partial_kernel<<<gscan, 512>>>(n);
    dim3 goff((n + 255) / 256, 2);
    add_offsets_kernel<<<goff, 256>>>(n, nb);
    fill_kernel<<<(2 * nE + 255) / 256, 256>>>(e0, e1, nE);

    int gemm_blocks = (n + 63) / 64;
    int agg_blocks = (n * 32 + 255) / 256;

    // --- iteration 1 ---
    gemm_kernel<<<gemm_blocks, 256, GEMM_SMEM_BYTES>>>(emb, t1, t2, t3, p_emb1, p_Y, n);
    agg_kernel<<<agg_blocks, 256>>>(p_Y, p_emb1, n);

    // --- iteration 2 ---
    gemm_kernel<<<gemm_blocks, 256, GEMM_SMEM_BYTES>>>(p_emb1, t1, t2, t3, out, p_Y, n);
    agg_kernel<<<agg_blocks, 256>>>(p_Y, out, n);
}